// round 9
// baseline (speedup 1.0000x reference)
#include <cuda_runtime.h>
#include <math.h>

#define Bq 8
#define Sq 1024
#define Dq 1024
#define Fq 3584
#define Eq 2
#define NB 296
#define NT 448
#define NW 14
#define EPSq 1e-6f

typedef unsigned long long ull;

// ---------------- device scratch (no allocation) ----------------
__device__ ull   g_pvu[64 * 4 * Dq];        // v0 partials [ic*4+p][j] (b-pairs)
__device__ float g_attn[Bq * Dq];           // attn output (atomic)
__device__ float g_accg[Eq * Bq * Fq];      // gate acc (atomic)
__device__ float g_accu[Eq * Bq * Fq];      // up acc (atomic)
__device__ float g_y[Bq * Dq];              // moe output (atomic)
__device__ unsigned g_barc = 0;
__device__ unsigned g_barg = 0;
__device__ unsigned g_ctr[4] = {0, 0, 0, 0}; // steal counters: A2, B, C2, D

// ---------------- f32x2 helpers ----------------
__device__ __forceinline__ ull pack2(float lo, float hi) {
    ull r;
    asm("mov.b64 %0, {%1, %2};" : "=l"(r) : "r"(__float_as_uint(lo)), "r"(__float_as_uint(hi)));
    return r;
}
__device__ __forceinline__ void unpack2(ull v, float& lo, float& hi) {
    unsigned a, b;
    asm("mov.b64 {%0, %1}, %2;" : "=r"(a), "=r"(b) : "l"(v));
    lo = __uint_as_float(a); hi = __uint_as_float(b);
}
#define FMA2(d, a, b) asm("fma.rn.f32x2 %0, %1, %2, %0;" : "+l"(d) : "l"(a), "l"(b))
#define ADD2(d, a)    asm("add.rn.f32x2 %0, %0, %1;"     : "+l"(d) : "l"(a))

// ---------------- software grid barrier ----------------
__device__ __forceinline__ void grid_bar() {
    __syncthreads();
    if (threadIdx.x == 0) {
        __threadfence();
        unsigned old = *(volatile unsigned*)&g_barg;
        if (atomicAdd(&g_barc, 1u) == (unsigned)gridDim.x - 1u) {
            g_barc = 0;
            __threadfence();
            atomicExch(&g_barg, old + 1u);
        } else {
            while (*(volatile unsigned*)&g_barg == old) __nanosleep(64);
        }
        __threadfence();
    }
    __syncthreads();
}

// ---------------- multi-value block reduction (14 warps) ----------
template <int NV>
__device__ __forceinline__ void breduce(const float* v, float* s_red, float* s_out) {
    int lane = threadIdx.x & 31, w = threadIdx.x >> 5;
#pragma unroll
    for (int k = 0; k < NV; k++) {
        float x = v[k];
#pragma unroll
        for (int o = 16; o; o >>= 1) x += __shfl_xor_sync(0xffffffffu, x, o);
        if (lane == 0) s_red[k * NW + w] = x;
    }
    __syncthreads();
    if (threadIdx.x < NV) {
        float s = 0.f;
#pragma unroll
        for (int j = 0; j < NW; j++) s += s_red[threadIdx.x * NW + j];
        s_out[threadIdx.x] = s;
    }
    __syncthreads();
}

__global__ void __launch_bounds__(NT, 2) fused_all(
    const float* __restrict__ hidden, const float* __restrict__ ln1w,
    const float* __restrict__ vw, const float* __restrict__ ow,
    const float* __restrict__ ln2w, const float* __restrict__ rw,
    const float* __restrict__ gw, const float* __restrict__ uw,
    const float* __restrict__ dw, const float* __restrict__ flnw,
    const float* __restrict__ sw, float* __restrict__ out)
{
    __shared__ float s_ht[Dq * Bq];     // 32KB: h1/h2 transposed [d][b]
    __shared__ float s_comb[112 * 2 * 8]; // 7KB: C2 half-combine [mat][fl][b]
    __shared__ float s_t[56 * 8];       // D t-vector [fl][b]
    __shared__ float s_v[16 * Bq];      // B v0 chunk
    __shared__ float s_red[16 * NW];
    __shared__ float s_out[16];
    __shared__ float s_rs[Bq];
    __shared__ int   s_sel[Bq];
    __shared__ float s_tw[Bq];
    __shared__ unsigned s_task;

    const int tid = threadIdx.x;
    const int blk = blockIdx.x;
    ull* s_htu = (ull*)s_ht;
    ull* s_vu  = (ull*)s_v;
    ull* s_tu  = (ull*)s_t;
    ull* s_cu  = (ull*)s_comb;

    // ============ Stage A0: zero atomic accumulators ============
    for (int idx = blk * NT + tid; idx < Eq * Bq * Fq; idx += NB * NT) {
        g_accg[idx] = 0.f; g_accu[idx] = 0.f;
    }
    for (int idx = blk * NT + tid; idx < Bq * Dq; idx += NB * NT) {
        g_attn[idx] = 0.f; g_y[idx] = 0.f;
    }

    // ============ A1: redundant h1 = rmsnorm(x0)*ln1_w -> s_ht[d][b] ============
    {
        float ss[Bq];
#pragma unroll
        for (int b = 0; b < Bq; b++) ss[b] = 0.f;
        for (int d = tid; d < Dq; d += NT) {
#pragma unroll
            for (int b = 0; b < Bq; b++) {
                float v = hidden[(size_t)b * Sq * Dq + d];
                ss[b] += v * v;
            }
        }
        breduce<Bq>(ss, s_red, s_out);
        if (tid < Bq) s_rs[tid] = rsqrtf(s_out[tid] * (1.f / Dq) + EPSq);
        __syncthreads();
        for (int d = tid; d < Dq; d += NT) {
            float lw = ln1w[d];
#pragma unroll
            for (int b = 0; b < Bq; b++)
                s_ht[d * Bq + b] = hidden[(size_t)b * Sq * Dq + d] * s_rs[b] * lw;
        }
        __syncthreads();
    }

    // ============ A2 (steal): v0 partials. 256 tasks: 64 ic(16) x 4 jc ============
    while (true) {
        __syncthreads();
        if (tid == 0) s_task = atomicAdd(&g_ctr[0], 1u);
        __syncthreads();
        unsigned t = s_task;
        if (t >= 256u) break;
        if (tid < 256) {
            int ic = t >> 2, jc = t & 3;
            int j = jc * 256 + tid, ib = ic * 16;
            float w[16];
#pragma unroll
            for (int u = 0; u < 16; u++) w[u] = vw[(size_t)(ib + u) * Dq + j];
            ull acc[4] = {0, 0, 0, 0};
#pragma unroll
            for (int u = 0; u < 16; u++) {
                ull w2 = pack2(w[u], w[u]);
#pragma unroll
                for (int p = 0; p < 4; p++) FMA2(acc[p], s_htu[(ib + u) * 4 + p], w2);
            }
#pragma unroll
            for (int p = 0; p < 4; p++) g_pvu[(size_t)(ic * 4 + p) * Dq + j] = acc[p];
        }
    }
    grid_bar();

    // ============ B (steal): attn = v0 @ o_w. 256 tasks ============
    while (true) {
        __syncthreads();
        if (tid == 0) s_task = atomicAdd(&g_ctr[1], 1u);
        __syncthreads();
        unsigned t = s_task;
        if (t >= 256u) break;
        int ic = t >> 2, jc = t & 3;
        int ib = ic * 16;
        if (tid < 64) {
            int i = tid >> 2, p = tid & 3;
            ull s = 0;
#pragma unroll 8
            for (int c = 0; c < 64; c++) {
                ull v = g_pvu[(size_t)(c * 4 + p) * Dq + ib + i];
                ADD2(s, v);
            }
            s_vu[i * 4 + p] = s;
        }
        __syncthreads();
        if (tid < 256) {
            int j = jc * 256 + tid;
            float w[16];
#pragma unroll
            for (int u = 0; u < 16; u++) w[u] = ow[(size_t)(ib + u) * Dq + j];
            ull acc[4] = {0, 0, 0, 0};
#pragma unroll
            for (int u = 0; u < 16; u++) {
                ull w2 = pack2(w[u], w[u]);
#pragma unroll
                for (int p = 0; p < 4; p++) FMA2(acc[p], s_vu[u * 4 + p], w2);
            }
#pragma unroll
            for (int p = 0; p < 4; p++) {
                float lo, hi; unpack2(acc[p], lo, hi);
                atomicAdd(&g_attn[(2 * p) * Dq + j], lo);
                atomicAdd(&g_attn[(2 * p + 1) * Dq + j], hi);
            }
        }
    }
    grid_bar();

    // ============ C1: xmid -> h2 (s_ht) + router ============
    {
        __syncthreads();
        float ss[Bq];
#pragma unroll
        for (int b = 0; b < Bq; b++) ss[b] = 0.f;
        for (int d = tid; d < Dq; d += NT) {
#pragma unroll
            for (int b = 0; b < Bq; b++) {
                float v = hidden[(size_t)b * Sq * Dq + d] + g_attn[b * Dq + d];
                ss[b] += v * v;
            }
        }
        breduce<Bq>(ss, s_red, s_out);
        if (tid < Bq) s_rs[tid] = rsqrtf(s_out[tid] * (1.f / Dq) + EPSq);
        __syncthreads();
        float l[16];
#pragma unroll
        for (int k = 0; k < 16; k++) l[k] = 0.f;
        for (int d = tid; d < Dq; d += NT) {
            float r0 = rw[d * 2 + 0], r1 = rw[d * 2 + 1], w2d = ln2w[d];
#pragma unroll
            for (int b = 0; b < Bq; b++) {
                float xm = hidden[(size_t)b * Sq * Dq + d] + g_attn[b * Dq + d];
                float h2 = xm * s_rs[b] * w2d;
                s_ht[d * Bq + b] = h2;
                l[b]     = fmaf(h2, r0, l[b]);
                l[8 + b] = fmaf(h2, r1, l[8 + b]);
            }
        }
        breduce<16>(l, s_red, s_out);
        if (tid < Bq) {
            float l0 = s_out[tid], l1 = s_out[8 + tid];
            s_sel[tid] = (l1 > l0) ? 1 : 0;
            s_tw[tid]  = 1.f / (1.f + expf(-fabsf(l0 - l1)));
        }
        __syncthreads();
    }

    bool usedE[Eq];
#pragma unroll
    for (int e = 0; e < Eq; e++) {
        bool u = false;
#pragma unroll
        for (int b = 0; b < Bq; b++) u |= (s_sel[b] == e);
        usedE[e] = u;
    }

    // ==== C2 (steal): gate+up. 512 tasks: e x 8 ic(128) x 32 fc(112f) ====
    {
        const int mat  = tid / 224;
        const int rr   = tid % 224;
        const int half = rr / 112;
        const int fl   = rr % 112;
        while (true) {
            __syncthreads();
            if (tid == 0) s_task = atomicAdd(&g_ctr[2], 1u);
            __syncthreads();
            unsigned t = s_task;
            if (t >= 512u) break;
            int e = t >> 8, r = t & 255, ic = r >> 5, fc = r & 31;
            if (!usedE[e]) continue;
            int f  = fc * 112 + fl;
            int ib = ic * 128 + half * 64;
            const float* wp = (mat ? uw : gw) + (size_t)e * Dq * Fq + f;
            ull acc[4] = {0, 0, 0, 0};
            for (int i8 = 0; i8 < 64; i8 += 8) {
                int i = ib + i8;
                float w[8];
#pragma unroll
                for (int u = 0; u < 8; u++) w[u] = wp[(size_t)(i + u) * Fq];
#pragma unroll
                for (int u = 0; u < 8; u++) {
                    ull w2 = pack2(w[u], w[u]);
#pragma unroll
                    for (int p = 0; p < 4; p++) FMA2(acc[p], s_htu[(i + u) * 4 + p], w2);
                }
            }
            if (half == 1) {
#pragma unroll
                for (int q = 0; q < 4; q++) s_cu[(mat * 112 + fl) * 4 + q] = acc[q];
            }
            __syncthreads();
            if (half == 0) {
#pragma unroll
                for (int q = 0; q < 4; q++) ADD2(acc[q], s_cu[(mat * 112 + fl) * 4 + q]);
                float* dst = (mat ? g_accu : g_accg) + (size_t)e * Bq * Fq + f;
#pragma unroll
                for (int p = 0; p < 4; p++) {
                    float lo, hi; unpack2(acc[p], lo, hi);
                    atomicAdd(&dst[(size_t)(2 * p) * Fq], lo);
                    atomicAdd(&dst[(size_t)(2 * p + 1) * Fq], hi);
                }
            }
        }
    }
    grid_bar();

    // ==== D (steal): silu/mask + down. 512 tasks: e x 64 fc(56f) x 4 dc(256d) ====
    while (true) {
        __syncthreads();
        if (tid == 0) s_task = atomicAdd(&g_ctr[3], 1u);
        __syncthreads();
        unsigned t = s_task;
        if (t >= 512u) break;
        int e = t >> 8, r = t & 255, fc = r >> 2, dc = r & 3;
        if (!usedE[e]) continue;
        int f0 = fc * 56, d0 = dc * 256;
        {   // t-vector: 56 x 8 = 448 = one elem per thread
            int fl = tid >> 3, b = tid & 7;
            float tv = 0.f;
            if (s_sel[b] == e) {
                int f = f0 + fl;
                float gg = g_accg[((size_t)e * Bq + b) * Fq + f];
                float uu = g_accu[((size_t)e * Bq + b) * Fq + f];
                tv = s_tw[b] * gg * (1.f / (1.f + expf(-gg))) * uu;
            }
            s_t[fl * 8 + b] = tv;
        }
        __syncthreads();
        if (tid < 256) {
            const float* dp = dw + ((size_t)e * Fq + f0) * Dq + d0 + tid;
            ull acc[4] = {0, 0, 0, 0};
            for (int f8 = 0; f8 < 56; f8 += 8) {
                float w[8];
#pragma unroll
                for (int u = 0; u < 8; u++) w[u] = dp[(size_t)(f8 + u) * Dq];
#pragma unroll
                for (int u = 0; u < 8; u++) {
                    ull w2 = pack2(w[u], w[u]);
#pragma unroll
                    for (int p = 0; p < 4; p++) FMA2(acc[p], s_tu[(f8 + u) * 4 + p], w2);
                }
            }
#pragma unroll
            for (int p = 0; p < 4; p++) {
                float lo, hi; unpack2(acc[p], lo, hi);
                atomicAdd(&g_y[(2 * p) * Dq + d0 + tid], lo);
                atomicAdd(&g_y[(2 * p + 1) * Dq + d0 + tid], hi);
            }
        }
    }
    grid_bar();

    // reset steal counters for next (graph-replayed) launch
    if (blk == NB - 1 && tid == 0) {
        g_ctr[0] = 0; g_ctr[1] = 0; g_ctr[2] = 0; g_ctr[3] = 0;
    }

    // ============ E: final rmsnorm + score head (8 blocks) ============
    if (blk < Bq) {
        int b = blk;
        float ssv[1]; ssv[0] = 0.f;
        for (int d = tid; d < Dq; d += NT) {
            float v = hidden[(size_t)b * Sq * Dq + d] + g_attn[b * Dq + d] + g_y[b * Dq + d];
            ssv[0] += v * v;
        }
        breduce<1>(ssv, s_red, s_out);
        if (tid == 0) s_rs[0] = rsqrtf(s_out[0] * (1.f / Dq) + EPSq);
        __syncthreads();
        float rs = s_rs[0];
        float p[2]; p[0] = 0.f; p[1] = 0.f;
        for (int d = tid; d < Dq; d += NT) {
            float v = hidden[(size_t)b * Sq * Dq + d] + g_attn[b * Dq + d] + g_y[b * Dq + d];
            float xn = v * rs * flnw[d];
            p[0] = fmaf(xn, sw[d * 2 + 0], p[0]);
            p[1] = fmaf(xn, sw[d * 2 + 1], p[1]);
        }
        breduce<2>(p, s_red, s_out);
        if (tid == 0) {
            out[b * 2 + 0] = s_out[0];
            out[b * 2 + 1] = s_out[1];
        }
    }
}

// ---------------- launch ----------------
extern "C" void kernel_launch(void* const* d_in, const int* in_sizes, int n_in,
                              void* d_out, int out_size) {
    (void)in_sizes; (void)n_in; (void)out_size;
    const float* hidden = (const float*)d_in[0];
    const float* ln1w   = (const float*)d_in[1];
    // d_in[2]=q_w, d_in[3]=k_w: provably unused (causal token-0 softmax == 1)
    const float* vw     = (const float*)d_in[4];
    const float* ow     = (const float*)d_in[5];
    const float* ln2w   = (const float*)d_in[6];
    const float* rw     = (const float*)d_in[7];
    const float* gw     = (const float*)d_in[8];
    const float* uw     = (const float*)d_in[9];
    const float* dw     = (const float*)d_in[10];
    const float* flnw   = (const float*)d_in[11];
    const float* sw     = (const float*)d_in[12];
    float* out = (float*)d_out;

    fused_all<<<NB, NT>>>(hidden, ln1w, vw, ow, ln2w, rw, gw, uw, dw, flnw, sw, out);
}

// round 10
// speedup vs baseline: 1.2226x; 1.2226x over previous
#include <cuda_runtime.h>
#include <math.h>

#define Bq 8
#define Sq 1024
#define Dq 1024
#define Fq 3584
#define Eq 2
#define EPSq 1e-6f

typedef unsigned long long ull;

// ---------------- device scratch (no allocation) ----------------
__device__ ull   g_pvu[64 * 4 * Dq];        // v0 partials [ic*4+p][j] (b-pairs)
__device__ float g_attn[Bq * Dq];           // attn output (atomic)
__device__ float g_accg[Eq * Bq * Fq];      // gate acc (atomic)
__device__ float g_accu[Eq * Bq * Fq];      // up acc (atomic)
__device__ float g_y[Bq * Dq];              // moe output (atomic)
__device__ int   g_selG[Bq];                // router selection
__device__ float g_twG[Bq];                 // router top weight

// ---------------- f32x2 helpers ----------------
__device__ __forceinline__ ull pack2(float lo, float hi) {
    ull r;
    asm("mov.b64 %0, {%1, %2};" : "=l"(r) : "r"(__float_as_uint(lo)), "r"(__float_as_uint(hi)));
    return r;
}
__device__ __forceinline__ void unpack2(ull v, float& lo, float& hi) {
    unsigned a, b;
    asm("mov.b64 {%0, %1}, %2;" : "=r"(a), "=r"(b) : "l"(v));
    lo = __uint_as_float(a); hi = __uint_as_float(b);
}
#define FMA2(d, a, b) asm("fma.rn.f32x2 %0, %1, %2, %0;" : "+l"(d) : "l"(a), "l"(b))
#define ADD2(d, a)    asm("add.rn.f32x2 %0, %0, %1;"     : "+l"(d) : "l"(a))

// ---------------- multi-value block reduction ----------
template <int NV, int NWP>
__device__ __forceinline__ void breduce(const float* v, float* s_red, float* s_out) {
    int lane = threadIdx.x & 31, w = threadIdx.x >> 5;
#pragma unroll
    for (int k = 0; k < NV; k++) {
        float x = v[k];
#pragma unroll
        for (int o = 16; o; o >>= 1) x += __shfl_xor_sync(0xffffffffu, x, o);
        if (lane == 0) s_red[k * NWP + w] = x;
    }
    __syncthreads();
    if (threadIdx.x < NV) {
        float s = 0.f;
#pragma unroll
        for (int j = 0; j < NWP; j++) s += s_red[threadIdx.x * NWP + j];
        s_out[threadIdx.x] = s;
    }
    __syncthreads();
}

// ============ K1: zero accs + h1 = rmsnorm(x0)*ln1_w + v0 partials ============
__global__ void __launch_bounds__(256) k1_prep_v(
    const float* __restrict__ hidden, const float* __restrict__ ln1w,
    const float* __restrict__ vw)
{
    __shared__ float s_ht[Dq * Bq];
    __shared__ float s_red[8 * 8];
    __shared__ float s_out[8];
    __shared__ float s_rs[Bq];
    const int tid = threadIdx.x, blk = blockIdx.x;
    ull* s_htu = (ull*)s_ht;

    // zero atomic accumulators
    for (int idx = blk * 256 + tid; idx < Eq * Bq * Fq; idx += 256 * 256) {
        g_accg[idx] = 0.f; g_accu[idx] = 0.f;
    }
    for (int idx = blk * 256 + tid; idx < Bq * Dq; idx += 256 * 256) {
        g_attn[idx] = 0.f; g_y[idx] = 0.f;
    }

    // A1: redundant h1
    float ss[Bq];
#pragma unroll
    for (int b = 0; b < Bq; b++) ss[b] = 0.f;
#pragma unroll
    for (int it = 0; it < 4; it++) {
        int d = tid + it * 256;
#pragma unroll
        for (int b = 0; b < Bq; b++) {
            float v = hidden[(size_t)b * Sq * Dq + d];
            ss[b] += v * v;
        }
    }
    breduce<8, 8>(ss, s_red, s_out);
    if (tid < Bq) s_rs[tid] = rsqrtf(s_out[tid] * (1.f / Dq) + EPSq);
    __syncthreads();
#pragma unroll
    for (int it = 0; it < 4; it++) {
        int d = tid + it * 256;
        float lw = ln1w[d];
#pragma unroll
        for (int b = 0; b < Bq; b++)
            s_ht[d * Bq + b] = hidden[(size_t)b * Sq * Dq + d] * s_rs[b] * lw;
    }
    __syncthreads();

    // A2: v0 partials. 256 blocks: 64 ic(16) x 4 jc(256)
    int ic = blk >> 2, jc = blk & 3;
    int j = jc * 256 + tid, ib = ic * 16;
    float w[16];
#pragma unroll
    for (int u = 0; u < 16; u++) w[u] = vw[(size_t)(ib + u) * Dq + j];
    ull acc[4] = {0, 0, 0, 0};
#pragma unroll
    for (int u = 0; u < 16; u++) {
        ull w2 = pack2(w[u], w[u]);
#pragma unroll
        for (int p = 0; p < 4; p++) FMA2(acc[p], s_htu[(ib + u) * 4 + p], w2);
    }
#pragma unroll
    for (int p = 0; p < 4; p++) g_pvu[(size_t)(ic * 4 + p) * Dq + j] = acc[p];
}

// ============ K2: attn = v0 @ o_w ============
__global__ void __launch_bounds__(256) k2_o(const float* __restrict__ ow)
{
    __shared__ float s_v[16 * Bq];
    const int tid = threadIdx.x, blk = blockIdx.x;
    ull* s_vu = (ull*)s_v;
    int ic = blk >> 2, jc = blk & 3;
    int ib = ic * 16;
    if (tid < 64) {
        int i = tid >> 2, p = tid & 3;
        ull s = 0;
#pragma unroll 8
        for (int c = 0; c < 64; c++) {
            ull v = g_pvu[(size_t)(c * 4 + p) * Dq + ib + i];
            ADD2(s, v);
        }
        s_vu[i * 4 + p] = s;
    }
    __syncthreads();
    int j = jc * 256 + tid;
    float w[16];
#pragma unroll
    for (int u = 0; u < 16; u++) w[u] = ow[(size_t)(ib + u) * Dq + j];
    ull acc[4] = {0, 0, 0, 0};
#pragma unroll
    for (int u = 0; u < 16; u++) {
        ull w2 = pack2(w[u], w[u]);
#pragma unroll
        for (int p = 0; p < 4; p++) FMA2(acc[p], s_vu[u * 4 + p], w2);
    }
#pragma unroll
    for (int p = 0; p < 4; p++) {
        float lo, hi; unpack2(acc[p], lo, hi);
        atomicAdd(&g_attn[(2 * p) * Dq + j], lo);
        atomicAdd(&g_attn[(2 * p + 1) * Dq + j], hi);
    }
}

// ============ K3: C1 (h2 + router) + C2 gate/up ============
__global__ void __launch_bounds__(448, 2) k3_gateup(
    const float* __restrict__ hidden, const float* __restrict__ ln2w,
    const float* __restrict__ rw, const float* __restrict__ gw,
    const float* __restrict__ uw)
{
    __shared__ float s_ht[Dq * Bq];   // h2 [d][b]; later C2 combine buffer
    __shared__ float s_red[16 * 14];
    __shared__ float s_out[16];
    __shared__ float s_rs[Bq];
    __shared__ int   s_sel[Bq];
    __shared__ float s_tw[Bq];
    const int tid = threadIdx.x, blk = blockIdx.x;
    ull* s_htu = (ull*)s_ht;

    // C1: xmid -> h2 + router (redundant per block)
    {
        float ss[Bq];
#pragma unroll
        for (int b = 0; b < Bq; b++) ss[b] = 0.f;
        for (int d = tid; d < Dq; d += 448) {
#pragma unroll
            for (int b = 0; b < Bq; b++) {
                float v = hidden[(size_t)b * Sq * Dq + d] + g_attn[b * Dq + d];
                ss[b] += v * v;
            }
        }
        breduce<8, 14>(ss, s_red, s_out);
        if (tid < Bq) s_rs[tid] = rsqrtf(s_out[tid] * (1.f / Dq) + EPSq);
        __syncthreads();
        float l[16];
#pragma unroll
        for (int k = 0; k < 16; k++) l[k] = 0.f;
        for (int d = tid; d < Dq; d += 448) {
            float r0 = rw[d * 2 + 0], r1 = rw[d * 2 + 1], w2d = ln2w[d];
#pragma unroll
            for (int b = 0; b < Bq; b++) {
                float xm = hidden[(size_t)b * Sq * Dq + d] + g_attn[b * Dq + d];
                float h2 = xm * s_rs[b] * w2d;
                s_ht[d * Bq + b] = h2;
                l[b]     = fmaf(h2, r0, l[b]);
                l[8 + b] = fmaf(h2, r1, l[8 + b]);
            }
        }
        breduce<16, 14>(l, s_red, s_out);
        if (tid < Bq) {
            float l0 = s_out[tid], l1 = s_out[8 + tid];
            int sel = (l1 > l0) ? 1 : 0;
            float tw = 1.f / (1.f + expf(-fabsf(l0 - l1)));
            s_sel[tid] = sel; s_tw[tid] = tw;
            g_selG[tid] = sel; g_twG[tid] = tw;   // identical across blocks
        }
        __syncthreads();
    }

    bool usedE[Eq];
#pragma unroll
    for (int e = 0; e < Eq; e++) {
        bool u = false;
#pragma unroll
        for (int b = 0; b < Bq; b++) u |= (s_sel[b] == e);
        usedE[e] = u;
    }

    // C2: 256 blocks: e x 8 ic(128) x 16 fc(224); i split in 2 halves across threads
    int e = blk >> 7, r = blk & 127, ic = r >> 4, fc = r & 15;
    if (!usedE[e]) return;
    int half = tid / 224;
    int fl   = tid % 224;
    int f    = fc * 224 + fl;
    int ib   = ic * 128 + half * 64;
    const float* gp  = gw + (size_t)e * Dq * Fq + f;
    const float* upp = uw + (size_t)e * Dq * Fq + f;
    ull ag[4] = {0, 0, 0, 0}, au[4] = {0, 0, 0, 0};
    for (int i8 = 0; i8 < 64; i8 += 8) {
        int i = ib + i8;
        float wg[8], wu[8];
#pragma unroll
        for (int u = 0; u < 8; u++) wg[u] = gp[(size_t)(i + u) * Fq];
#pragma unroll
        for (int u = 0; u < 8; u++) wu[u] = upp[(size_t)(i + u) * Fq];
#pragma unroll
        for (int u = 0; u < 8; u++) {
            ull wg2 = pack2(wg[u], wg[u]);
            ull wu2 = pack2(wu[u], wu[u]);
#pragma unroll
            for (int p = 0; p < 4; p++) {
                ull h2 = s_htu[(i + u) * 4 + p];
                FMA2(ag[p], h2, wg2);
                FMA2(au[p], h2, wu2);
            }
        }
    }
    __syncthreads();            // all h2 reads done; reuse s_ht as combine buf
    ull* comb = s_htu;
    if (half == 1) {
#pragma unroll
        for (int q = 0; q < 4; q++) { comb[fl * 8 + q] = ag[q]; comb[fl * 8 + 4 + q] = au[q]; }
    }
    __syncthreads();
    if (half == 0) {
#pragma unroll
        for (int q = 0; q < 4; q++) { ADD2(ag[q], comb[fl * 8 + q]); ADD2(au[q], comb[fl * 8 + 4 + q]); }
#pragma unroll
        for (int p = 0; p < 4; p++) {
            float lo, hi;
            unpack2(ag[p], lo, hi);
            atomicAdd(&g_accg[((size_t)e * Bq + 2 * p) * Fq + f], lo);
            atomicAdd(&g_accg[((size_t)e * Bq + 2 * p + 1) * Fq + f], hi);
            unpack2(au[p], lo, hi);
            atomicAdd(&g_accu[((size_t)e * Bq + 2 * p) * Fq + f], lo);
            atomicAdd(&g_accu[((size_t)e * Bq + 2 * p + 1) * Fq + f], hi);
        }
    }
}

// ============ K4: silu/mask + down ============
__global__ void __launch_bounds__(256) k4_down(const float* __restrict__ dw)
{
    __shared__ float s_t[112 * 8];
    __shared__ int   s_sel[Bq];
    __shared__ float s_tw[Bq];
    const int tid = threadIdx.x, blk = blockIdx.x;
    ull* s_tu = (ull*)s_t;
    if (tid < Bq) { s_sel[tid] = g_selG[tid]; s_tw[tid] = g_twG[tid]; }
    __syncthreads();
    bool usedE[Eq];
#pragma unroll
    for (int e = 0; e < Eq; e++) {
        bool u = false;
#pragma unroll
        for (int b = 0; b < Bq; b++) u |= (s_sel[b] == e);
        usedE[e] = u;
    }
    int e = blk >> 7, r = blk & 127, fc = r >> 2, dc = r & 3;
    if (!usedE[e]) return;
    int f0 = fc * 112;
    for (int idx = tid; idx < 896; idx += 256) {
        int fl = idx >> 3, b = idx & 7;
        float tv = 0.f;
        if (s_sel[b] == e) {
            int f = f0 + fl;
            float gg = g_accg[((size_t)e * Bq + b) * Fq + f];
            float uu = g_accu[((size_t)e * Bq + b) * Fq + f];
            tv = s_tw[b] * gg * (1.f / (1.f + expf(-gg))) * uu;
        }
        s_t[fl * 8 + b] = tv;
    }
    __syncthreads();
    int d = dc * 256 + tid;
    const float* dp = dw + ((size_t)e * Fq + f0) * Dq + d;
    ull acc[4] = {0, 0, 0, 0};
    for (int f16 = 0; f16 < 112; f16 += 16) {
        float w[16];
#pragma unroll
        for (int u = 0; u < 16; u++) w[u] = dp[(size_t)(f16 + u) * Dq];
#pragma unroll
        for (int u = 0; u < 16; u++) {
            ull w2 = pack2(w[u], w[u]);
#pragma unroll
            for (int p = 0; p < 4; p++) FMA2(acc[p], s_tu[(f16 + u) * 4 + p], w2);
        }
    }
#pragma unroll
    for (int p = 0; p < 4; p++) {
        float lo, hi; unpack2(acc[p], lo, hi);
        atomicAdd(&g_y[(2 * p) * Dq + d], lo);
        atomicAdd(&g_y[(2 * p + 1) * Dq + d], hi);
    }
}

// ============ K5: final rmsnorm + score head ============
__global__ void __launch_bounds__(256) k5_final(
    const float* __restrict__ hidden, const float* __restrict__ flnw,
    const float* __restrict__ sw, float* __restrict__ out)
{
    __shared__ float s_red[8 * 8];
    __shared__ float s_out[8];
    __shared__ float s_rs[1];
    const int tid = threadIdx.x, b = blockIdx.x;
    float xr[4];
    float ssv[1]; ssv[0] = 0.f;
#pragma unroll
    for (int it = 0; it < 4; it++) {
        int d = tid + it * 256;
        xr[it] = hidden[(size_t)b * Sq * Dq + d] + g_attn[b * Dq + d] + g_y[b * Dq + d];
        ssv[0] += xr[it] * xr[it];
    }
    breduce<1, 8>(ssv, s_red, s_out);
    if (tid == 0) s_rs[0] = rsqrtf(s_out[0] * (1.f / Dq) + EPSq);
    __syncthreads();
    float rs = s_rs[0];
    float p[2]; p[0] = 0.f; p[1] = 0.f;
#pragma unroll
    for (int it = 0; it < 4; it++) {
        int d = tid + it * 256;
        float xn = xr[it] * rs * flnw[d];
        p[0] = fmaf(xn, sw[d * 2 + 0], p[0]);
        p[1] = fmaf(xn, sw[d * 2 + 1], p[1]);
    }
    breduce<2, 8>(p, s_red, s_out);
    if (tid == 0) {
        out[b * 2 + 0] = s_out[0];
        out[b * 2 + 1] = s_out[1];
    }
}

// ---------------- launch ----------------
extern "C" void kernel_launch(void* const* d_in, const int* in_sizes, int n_in,
                              void* d_out, int out_size) {
    (void)in_sizes; (void)n_in; (void)out_size;
    const float* hidden = (const float*)d_in[0];
    const float* ln1w   = (const float*)d_in[1];
    // d_in[2]=q_w, d_in[3]=k_w: provably unused (causal token-0 softmax == 1)
    const float* vw     = (const float*)d_in[4];
    const float* ow     = (const float*)d_in[5];
    const float* ln2w   = (const float*)d_in[6];
    const float* rw     = (const float*)d_in[7];
    const float* gw     = (const float*)d_in[8];
    const float* uw     = (const float*)d_in[9];
    const float* dw     = (const float*)d_in[10];
    const float* flnw   = (const float*)d_in[11];
    const float* sw     = (const float*)d_in[12];
    float* out = (float*)d_out;

    k1_prep_v<<<256, 256>>>(hidden, ln1w, vw);
    k2_o<<<256, 256>>>(ow);
    k3_gateup<<<256, 448>>>(hidden, ln2w, rw, gw, uw);
    k4_down<<<256, 256>>>(dw);
    k5_final<<<Bq, 256>>>(hidden, flnw, sw, out);
}

// round 11
// speedup vs baseline: 1.3287x; 1.0868x over previous
#include <cuda_runtime.h>
#include <math.h>

#define Bq 8
#define Sq 1024
#define Dq 1024
#define Fq 3584
#define Eq 2
#define EPSq 1e-6f

typedef unsigned long long ull;

// ---------------- device scratch (no allocation) ----------------
__device__ ull   g_pvu[64 * 4 * Dq];        // v0 partials [ic*4+p][j] (b-pairs)
__device__ float g_attn[Bq * Dq];           // attn output (atomic)
__device__ float g_h2t[Dq * Bq];            // h2 transposed [d][b]
__device__ float g_accg[Eq * Bq * Fq];      // gate acc (atomic)
__device__ float g_accu[Eq * Bq * Fq];      // up acc (atomic)
__device__ float g_y[Bq * Dq];              // moe output (atomic)
__device__ int   g_selG[Bq];                // router selection
__device__ float g_twG[Bq];                 // router top weight

// ---------------- f32x2 helpers ----------------
__device__ __forceinline__ ull pack2(float lo, float hi) {
    ull r;
    asm("mov.b64 %0, {%1, %2};" : "=l"(r) : "r"(__float_as_uint(lo)), "r"(__float_as_uint(hi)));
    return r;
}
__device__ __forceinline__ void unpack2(ull v, float& lo, float& hi) {
    unsigned a, b;
    asm("mov.b64 {%0, %1}, %2;" : "=r"(a), "=r"(b) : "l"(v));
    lo = __uint_as_float(a); hi = __uint_as_float(b);
}
#define FMA2(d, a, b) asm("fma.rn.f32x2 %0, %1, %2, %0;" : "+l"(d) : "l"(a), "l"(b))
#define ADD2(d, a)    asm("add.rn.f32x2 %0, %0, %1;"     : "+l"(d) : "l"(a))

// ---------------- multi-value block reduction ----------
template <int NV, int NWP>
__device__ __forceinline__ void breduce(const float* v, float* s_red, float* s_out) {
    int lane = threadIdx.x & 31, w = threadIdx.x >> 5;
#pragma unroll
    for (int k = 0; k < NV; k++) {
        float x = v[k];
#pragma unroll
        for (int o = 16; o; o >>= 1) x += __shfl_xor_sync(0xffffffffu, x, o);
        if (lane == 0) s_red[k * NWP + w] = x;
    }
    __syncthreads();
    if (threadIdx.x < NV) {
        float s = 0.f;
#pragma unroll
        for (int j = 0; j < NWP; j++) s += s_red[threadIdx.x * NWP + j];
        s_out[threadIdx.x] = s;
    }
    __syncthreads();
}

// ============ K1: zero accs + h1 = rmsnorm(x0)*ln1_w + v0 partials ============
__global__ void __launch_bounds__(256) k1_prep_v(
    const float* __restrict__ hidden, const float* __restrict__ ln1w,
    const float* __restrict__ vw)
{
    __shared__ float s_ht[Dq * Bq];
    __shared__ float s_red[8 * 8];
    __shared__ float s_out[8];
    __shared__ float s_rs[Bq];
    const int tid = threadIdx.x, blk = blockIdx.x;
    ull* s_htu = (ull*)s_ht;

    for (int idx = blk * 256 + tid; idx < Eq * Bq * Fq; idx += 256 * 256) {
        g_accg[idx] = 0.f; g_accu[idx] = 0.f;
    }
    for (int idx = blk * 256 + tid; idx < Bq * Dq; idx += 256 * 256) {
        g_attn[idx] = 0.f; g_y[idx] = 0.f;
    }

    float ss[Bq];
#pragma unroll
    for (int b = 0; b < Bq; b++) ss[b] = 0.f;
#pragma unroll
    for (int it = 0; it < 4; it++) {
        int d = tid + it * 256;
#pragma unroll
        for (int b = 0; b < Bq; b++) {
            float v = hidden[(size_t)b * Sq * Dq + d];
            ss[b] += v * v;
        }
    }
    breduce<8, 8>(ss, s_red, s_out);
    if (tid < Bq) s_rs[tid] = rsqrtf(s_out[tid] * (1.f / Dq) + EPSq);
    __syncthreads();
#pragma unroll
    for (int it = 0; it < 4; it++) {
        int d = tid + it * 256;
        float lw = ln1w[d];
#pragma unroll
        for (int b = 0; b < Bq; b++)
            s_ht[d * Bq + b] = hidden[(size_t)b * Sq * Dq + d] * s_rs[b] * lw;
    }
    __syncthreads();

    int ic = blk >> 2, jc = blk & 3;
    int j = jc * 256 + tid, ib = ic * 16;
    float w[16];
#pragma unroll
    for (int u = 0; u < 16; u++) w[u] = vw[(size_t)(ib + u) * Dq + j];
    ull acc[4] = {0, 0, 0, 0};
#pragma unroll
    for (int u = 0; u < 16; u++) {
        ull w2 = pack2(w[u], w[u]);
#pragma unroll
        for (int p = 0; p < 4; p++) FMA2(acc[p], s_htu[(ib + u) * 4 + p], w2);
    }
#pragma unroll
    for (int p = 0; p < 4; p++) g_pvu[(size_t)(ic * 4 + p) * Dq + j] = acc[p];
}

// ============ K2: attn = v0 @ o_w ============
__global__ void __launch_bounds__(256) k2_o(const float* __restrict__ ow)
{
    __shared__ float s_v[16 * Bq];
    const int tid = threadIdx.x, blk = blockIdx.x;
    ull* s_vu = (ull*)s_v;
    int ic = blk >> 2, jc = blk & 3;
    int ib = ic * 16;
    if (tid < 64) {
        int i = tid >> 2, p = tid & 3;
        ull s = 0;
#pragma unroll 8
        for (int c = 0; c < 64; c++) {
            ull v = g_pvu[(size_t)(c * 4 + p) * Dq + ib + i];
            ADD2(s, v);
        }
        s_vu[i * 4 + p] = s;
    }
    __syncthreads();
    int j = jc * 256 + tid;
    float w[16];
#pragma unroll
    for (int u = 0; u < 16; u++) w[u] = ow[(size_t)(ib + u) * Dq + j];
    ull acc[4] = {0, 0, 0, 0};
#pragma unroll
    for (int u = 0; u < 16; u++) {
        ull w2 = pack2(w[u], w[u]);
#pragma unroll
        for (int p = 0; p < 4; p++) FMA2(acc[p], s_vu[u * 4 + p], w2);
    }
#pragma unroll
    for (int p = 0; p < 4; p++) {
        float lo, hi; unpack2(acc[p], lo, hi);
        atomicAdd(&g_attn[(2 * p) * Dq + j], lo);
        atomicAdd(&g_attn[(2 * p + 1) * Dq + j], hi);
    }
}

// ============ K2b: xmid -> h2 (global, transposed) + router. 8 blocks ============
__global__ void __launch_bounds__(256) k2b_h2(
    const float* __restrict__ hidden, const float* __restrict__ ln2w,
    const float* __restrict__ rw)
{
    __shared__ float s_red[2 * 8];
    __shared__ float s_out[2];
    __shared__ float s_rs[1];
    const int tid = threadIdx.x, b = blockIdx.x;
    float xm[4];
    float ss[1]; ss[0] = 0.f;
#pragma unroll
    for (int it = 0; it < 4; it++) {
        int d = tid + it * 256;
        xm[it] = hidden[(size_t)b * Sq * Dq + d] + g_attn[b * Dq + d];
        ss[0] += xm[it] * xm[it];
    }
    breduce<1, 8>(ss, s_red, s_out);
    if (tid == 0) s_rs[0] = rsqrtf(s_out[0] * (1.f / Dq) + EPSq);
    __syncthreads();
    float rs = s_rs[0];
    float l[2]; l[0] = 0.f; l[1] = 0.f;
#pragma unroll
    for (int it = 0; it < 4; it++) {
        int d = tid + it * 256;
        float h2 = xm[it] * rs * ln2w[d];
        g_h2t[d * Bq + b] = h2;
        l[0] = fmaf(h2, rw[d * 2 + 0], l[0]);
        l[1] = fmaf(h2, rw[d * 2 + 1], l[1]);
    }
    breduce<2, 8>(l, s_red, s_out);
    if (tid == 0) {
        float l0 = s_out[0], l1 = s_out[1];
        g_selG[b] = (l1 > l0) ? 1 : 0;
        g_twG[b]  = 1.f / (1.f + expf(-fabsf(l0 - l1)));
    }
}

// ============ K3: gate|up matvec, double-buffered. 1024 blocks x 256 ============
// blk = e(1) x m(1) x ic(3 bits, 8 chunks of 128) x fc(5 bits, 32 chunks of 112)
__global__ void __launch_bounds__(256) k3_gateup(
    const float* __restrict__ gw, const float* __restrict__ uw)
{
    __shared__ float s_ht[Dq * Bq];       // h2 [d][b]
    __shared__ ull   s_comb[112 * 4];     // half-combine
    __shared__ int   s_sel[Bq];
    const int tid = threadIdx.x, blk = blockIdx.x;
    ull* s_htu = (ull*)s_ht;

    if (tid < Bq) s_sel[tid] = g_selG[tid];
    // load h2: 8192 floats = 2048 float4
#pragma unroll
    for (int i = 0; i < 8; i++)
        ((float4*)s_ht)[tid + i * 256] = ((const float4*)g_h2t)[tid + i * 256];
    __syncthreads();

    int e = blk >> 9, m = (blk >> 8) & 1, ic = (blk >> 5) & 7, fc = blk & 31;
    bool used = false;
#pragma unroll
    for (int b = 0; b < Bq; b++) used |= (s_sel[b] == e);
    if (!used) return;

    const bool active = tid < 224;
    const int half = tid / 112, fl = tid % 112;
    const int f = fc * 112 + fl;
    const int ib = ic * 128 + half * 64;
    ull acc[4] = {0, 0, 0, 0};
    if (active) {
        const float* wp = (m ? uw : gw) + (size_t)e * Dq * Fq + f;
        float wa[8], wb[8];
#pragma unroll
        for (int u = 0; u < 8; u++) wa[u] = wp[(size_t)(ib + u) * Fq];
#pragma unroll
        for (int r = 0; r < 8; r++) {
            if (r < 7) {
#pragma unroll
                for (int u = 0; u < 8; u++)
                    wb[u] = wp[(size_t)(ib + (r + 1) * 8 + u) * Fq];
            }
            int i = ib + r * 8;
#pragma unroll
            for (int u = 0; u < 8; u++) {
                ull w2 = pack2(wa[u], wa[u]);
#pragma unroll
                for (int p = 0; p < 4; p++) FMA2(acc[p], s_htu[(i + u) * 4 + p], w2);
            }
#pragma unroll
            for (int u = 0; u < 8; u++) wa[u] = wb[u];
        }
    }
    __syncthreads();
    if (active && half == 1) {
#pragma unroll
        for (int q = 0; q < 4; q++) s_comb[fl * 4 + q] = acc[q];
    }
    __syncthreads();
    if (active && half == 0) {
#pragma unroll
        for (int q = 0; q < 4; q++) ADD2(acc[q], s_comb[fl * 4 + q]);
        float* dst = (m ? g_accu : g_accg) + (size_t)e * Bq * Fq + f;
#pragma unroll
        for (int p = 0; p < 4; p++) {
            float lo, hi; unpack2(acc[p], lo, hi);
            atomicAdd(&dst[(size_t)(2 * p) * Fq], lo);
            atomicAdd(&dst[(size_t)(2 * p + 1) * Fq], hi);
        }
    }
}

// ============ K4: silu/mask + down, double-buffered. 512 blocks x 256 ============
// blk = e(1) x fc(6 bits, 64 chunks of 56) x dc(2 bits, 4 chunks of 256)
__global__ void __launch_bounds__(256) k4_down(const float* __restrict__ dw)
{
    __shared__ float s_t[56 * 8];
    __shared__ int   s_sel[Bq];
    __shared__ float s_tw[Bq];
    const int tid = threadIdx.x, blk = blockIdx.x;
    ull* s_tu = (ull*)s_t;
    if (tid < Bq) { s_sel[tid] = g_selG[tid]; s_tw[tid] = g_twG[tid]; }
    __syncthreads();
    int e = blk >> 8, fc = (blk >> 2) & 63, dc = blk & 3;
    bool used = false;
#pragma unroll
    for (int b = 0; b < Bq; b++) used |= (s_sel[b] == e);
    if (!used) return;
    int f0 = fc * 56;
    for (int idx = tid; idx < 448; idx += 256) {
        int fl = idx >> 3, b = idx & 7;
        float tv = 0.f;
        if (s_sel[b] == e) {
            int f = f0 + fl;
            float gg = g_accg[((size_t)e * Bq + b) * Fq + f];
            float uu = g_accu[((size_t)e * Bq + b) * Fq + f];
            tv = s_tw[b] * gg * (1.f / (1.f + expf(-gg))) * uu;
        }
        s_t[fl * 8 + b] = tv;
    }
    __syncthreads();
    int d = dc * 256 + tid;
    const float* dp = dw + ((size_t)e * Fq + f0) * Dq + d;
    ull acc[4] = {0, 0, 0, 0};
    float wa[8], wb[8];
#pragma unroll
    for (int u = 0; u < 8; u++) wa[u] = dp[(size_t)u * Dq];
#pragma unroll
    for (int r = 0; r < 7; r++) {
        if (r < 6) {
#pragma unroll
            for (int u = 0; u < 8; u++) wb[u] = dp[(size_t)((r + 1) * 8 + u) * Dq];
        }
#pragma unroll
        for (int u = 0; u < 8; u++) {
            ull w2 = pack2(wa[u], wa[u]);
#pragma unroll
            for (int p = 0; p < 4; p++) FMA2(acc[p], s_tu[(r * 8 + u) * 4 + p], w2);
        }
#pragma unroll
        for (int u = 0; u < 8; u++) wa[u] = wb[u];
    }
#pragma unroll
    for (int p = 0; p < 4; p++) {
        float lo, hi; unpack2(acc[p], lo, hi);
        atomicAdd(&g_y[(2 * p) * Dq + d], lo);
        atomicAdd(&g_y[(2 * p + 1) * Dq + d], hi);
    }
}

// ============ K5: final rmsnorm + score head ============
__global__ void __launch_bounds__(256) k5_final(
    const float* __restrict__ hidden, const float* __restrict__ flnw,
    const float* __restrict__ sw, float* __restrict__ out)
{
    __shared__ float s_red[8 * 8];
    __shared__ float s_out[8];
    __shared__ float s_rs[1];
    const int tid = threadIdx.x, b = blockIdx.x;
    float xr[4];
    float ssv[1]; ssv[0] = 0.f;
#pragma unroll
    for (int it = 0; it < 4; it++) {
        int d = tid + it * 256;
        xr[it] = hidden[(size_t)b * Sq * Dq + d] + g_attn[b * Dq + d] + g_y[b * Dq + d];
        ssv[0] += xr[it] * xr[it];
    }
    breduce<1, 8>(ssv, s_red, s_out);
    if (tid == 0) s_rs[0] = rsqrtf(s_out[0] * (1.f / Dq) + EPSq);
    __syncthreads();
    float rs = s_rs[0];
    float p[2]; p[0] = 0.f; p[1] = 0.f;
#pragma unroll
    for (int it = 0; it < 4; it++) {
        int d = tid + it * 256;
        float xn = xr[it] * rs * flnw[d];
        p[0] = fmaf(xn, sw[d * 2 + 0], p[0]);
        p[1] = fmaf(xn, sw[d * 2 + 1], p[1]);
    }
    breduce<2, 8>(p, s_red, s_out);
    if (tid == 0) {
        out[b * 2 + 0] = s_out[0];
        out[b * 2 + 1] = s_out[1];
    }
}

// ---------------- launch ----------------
extern "C" void kernel_launch(void* const* d_in, const int* in_sizes, int n_in,
                              void* d_out, int out_size) {
    (void)in_sizes; (void)n_in; (void)out_size;
    const float* hidden = (const float*)d_in[0];
    const float* ln1w   = (const float*)d_in[1];
    // d_in[2]=q_w, d_in[3]=k_w: provably unused (causal token-0 softmax == 1)
    const float* vw     = (const float*)d_in[4];
    const float* ow     = (const float*)d_in[5];
    const float* ln2w   = (const float*)d_in[6];
    const float* rw     = (const float*)d_in[7];
    const float* gw     = (const float*)d_in[8];
    const float* uw     = (const float*)d_in[9];
    const float* dw     = (const float*)d_in[10];
    const float* flnw   = (const float*)d_in[11];
    const float* sw     = (const float*)d_in[12];
    float* out = (float*)d_out;

    k1_prep_v<<<256, 256>>>(hidden, ln1w, vw);
    k2_o<<<256, 256>>>(ow);
    k2b_h2<<<Bq, 256>>>(hidden, ln2w, rw);
    k3_gateup<<<1024, 256>>>(gw, uw);
    k4_down<<<512, 256>>>(dw);
    k5_final<<<Bq, 256>>>(hidden, flnw, sw, out);
}

// round 12
// speedup vs baseline: 1.6383x; 1.2330x over previous
#include <cuda_runtime.h>
#include <math.h>

#define Bq 8
#define Sq 1024
#define Dq 1024
#define Fq 3584
#define Eq 2
#define EPSq 1e-6f

typedef unsigned long long ull;

// ---------------- device scratch (no allocation) ----------------
__device__ ull   g_pvu[64 * 4 * Dq];        // v0 partials [ic*4+p][j] (b-pairs)
__device__ float g_attn[Bq * Dq];           // attn output (atomic)
__device__ float g_h2t[Dq * Bq];            // h2 transposed [d][b]
__device__ float g_accg[Eq * Bq * Fq];      // gate acc (atomic)
__device__ float g_accu[Eq * Bq * Fq];      // up acc (atomic)
__device__ float g_y[Bq * Dq];              // moe output (atomic)
__device__ int   g_selG[Bq];                // router selection
__device__ float g_twG[Bq];                 // router top weight

// ---------------- f32x2 helpers ----------------
__device__ __forceinline__ ull pack2(float lo, float hi) {
    ull r;
    asm("mov.b64 %0, {%1, %2};" : "=l"(r) : "r"(__float_as_uint(lo)), "r"(__float_as_uint(hi)));
    return r;
}
__device__ __forceinline__ void unpack2(ull v, float& lo, float& hi) {
    unsigned a, b;
    asm("mov.b64 {%0, %1}, %2;" : "=r"(a), "=r"(b) : "l"(v));
    lo = __uint_as_float(a); hi = __uint_as_float(b);
}
#define FMA2(d, a, b) asm("fma.rn.f32x2 %0, %1, %2, %0;" : "+l"(d) : "l"(a), "l"(b))
#define ADD2(d, a)    asm("add.rn.f32x2 %0, %0, %1;"     : "+l"(d) : "l"(a))

// ---------------- multi-value block reduction ----------
template <int NV, int NWP>
__device__ __forceinline__ void breduce(const float* v, float* s_red, float* s_out) {
    int lane = threadIdx.x & 31, w = threadIdx.x >> 5;
#pragma unroll
    for (int k = 0; k < NV; k++) {
        float x = v[k];
#pragma unroll
        for (int o = 16; o; o >>= 1) x += __shfl_xor_sync(0xffffffffu, x, o);
        if (lane == 0) s_red[k * NWP + w] = x;
    }
    __syncthreads();
    if (threadIdx.x < NV) {
        float s = 0.f;
#pragma unroll
        for (int j = 0; j < NWP; j++) s += s_red[threadIdx.x * NWP + j];
        s_out[threadIdx.x] = s;
    }
    __syncthreads();
}

// ============ K1: zero accs + h1 = rmsnorm(x0)*ln1_w + v0 partials ============
__global__ void __launch_bounds__(256) k1_prep_v(
    const float* __restrict__ hidden, const float* __restrict__ ln1w,
    const float* __restrict__ vw)
{
    __shared__ float s_ht[Dq * Bq];
    __shared__ float s_red[8 * 8];
    __shared__ float s_out[8];
    __shared__ float s_rs[Bq];
    const int tid = threadIdx.x, blk = blockIdx.x;
    ull* s_htu = (ull*)s_ht;

    for (int idx = blk * 256 + tid; idx < Eq * Bq * Fq; idx += 256 * 256) {
        g_accg[idx] = 0.f; g_accu[idx] = 0.f;
    }
    for (int idx = blk * 256 + tid; idx < Bq * Dq; idx += 256 * 256) {
        g_attn[idx] = 0.f; g_y[idx] = 0.f;
    }

    float ss[Bq];
#pragma unroll
    for (int b = 0; b < Bq; b++) ss[b] = 0.f;
#pragma unroll
    for (int it = 0; it < 4; it++) {
        int d = tid + it * 256;
#pragma unroll
        for (int b = 0; b < Bq; b++) {
            float v = hidden[(size_t)b * Sq * Dq + d];
            ss[b] += v * v;
        }
    }
    breduce<8, 8>(ss, s_red, s_out);
    if (tid < Bq) s_rs[tid] = rsqrtf(s_out[tid] * (1.f / Dq) + EPSq);
    __syncthreads();
#pragma unroll
    for (int it = 0; it < 4; it++) {
        int d = tid + it * 256;
        float lw = ln1w[d];
#pragma unroll
        for (int b = 0; b < Bq; b++)
            s_ht[d * Bq + b] = hidden[(size_t)b * Sq * Dq + d] * s_rs[b] * lw;
    }
    __syncthreads();

    int ic = blk >> 2, jc = blk & 3;
    int j = jc * 256 + tid, ib = ic * 16;
    float w[16];
#pragma unroll
    for (int u = 0; u < 16; u++) w[u] = vw[(size_t)(ib + u) * Dq + j];
    ull acc[4] = {0, 0, 0, 0};
#pragma unroll
    for (int u = 0; u < 16; u++) {
        ull w2 = pack2(w[u], w[u]);
#pragma unroll
        for (int p = 0; p < 4; p++) FMA2(acc[p], s_htu[(ib + u) * 4 + p], w2);
    }
#pragma unroll
    for (int p = 0; p < 4; p++) g_pvu[(size_t)(ic * 4 + p) * Dq + j] = acc[p];
}

// ============ K2: attn = v0 @ o_w ============
__global__ void __launch_bounds__(256) k2_o(const float* __restrict__ ow)
{
    __shared__ float s_v[16 * Bq];
    const int tid = threadIdx.x, blk = blockIdx.x;
    ull* s_vu = (ull*)s_v;
    int ic = blk >> 2, jc = blk & 3;
    int ib = ic * 16;
    if (tid < 64) {
        int i = tid >> 2, p = tid & 3;
        ull s = 0;
#pragma unroll 8
        for (int c = 0; c < 64; c++) {
            ull v = g_pvu[(size_t)(c * 4 + p) * Dq + ib + i];
            ADD2(s, v);
        }
        s_vu[i * 4 + p] = s;
    }
    __syncthreads();
    int j = jc * 256 + tid;
    float w[16];
#pragma unroll
    for (int u = 0; u < 16; u++) w[u] = ow[(size_t)(ib + u) * Dq + j];
    ull acc[4] = {0, 0, 0, 0};
#pragma unroll
    for (int u = 0; u < 16; u++) {
        ull w2 = pack2(w[u], w[u]);
#pragma unroll
        for (int p = 0; p < 4; p++) FMA2(acc[p], s_vu[u * 4 + p], w2);
    }
#pragma unroll
    for (int p = 0; p < 4; p++) {
        float lo, hi; unpack2(acc[p], lo, hi);
        atomicAdd(&g_attn[(2 * p) * Dq + j], lo);
        atomicAdd(&g_attn[(2 * p + 1) * Dq + j], hi);
    }
}

// ============ K2b: xmid -> h2 (global, transposed) + router. 8 blocks ============
__global__ void __launch_bounds__(256) k2b_h2(
    const float* __restrict__ hidden, const float* __restrict__ ln2w,
    const float* __restrict__ rw)
{
    __shared__ float s_red[2 * 8];
    __shared__ float s_out[2];
    __shared__ float s_rs[1];
    const int tid = threadIdx.x, b = blockIdx.x;
    float xm[4];
    float ss[1]; ss[0] = 0.f;
#pragma unroll
    for (int it = 0; it < 4; it++) {
        int d = tid + it * 256;
        xm[it] = hidden[(size_t)b * Sq * Dq + d] + g_attn[b * Dq + d];
        ss[0] += xm[it] * xm[it];
    }
    breduce<1, 8>(ss, s_red, s_out);
    if (tid == 0) s_rs[0] = rsqrtf(s_out[0] * (1.f / Dq) + EPSq);
    __syncthreads();
    float rs = s_rs[0];
    float l[2]; l[0] = 0.f; l[1] = 0.f;
#pragma unroll
    for (int it = 0; it < 4; it++) {
        int d = tid + it * 256;
        float h2 = xm[it] * rs * ln2w[d];
        g_h2t[d * Bq + b] = h2;
        l[0] = fmaf(h2, rw[d * 2 + 0], l[0]);
        l[1] = fmaf(h2, rw[d * 2 + 1], l[1]);
    }
    breduce<2, 8>(l, s_red, s_out);
    if (tid == 0) {
        float l0 = s_out[0], l1 = s_out[1];
        g_selG[b] = (l1 > l0) ? 1 : 0;
        g_twG[b]  = 1.f / (1.f + expf(-fabsf(l0 - l1)));
    }
}

// ============ K3: gate|up matvec, float2 + double-buffered. 448 blocks ============
// blk: fc(14 chunks of 256 f) fastest, then ic(8 of 128 i), m, e. grid = 448.
__global__ void __launch_bounds__(256, 3) k3_gateup(
    const float* __restrict__ gw, const float* __restrict__ uw)
{
    __shared__ float s_h[128 * Bq];        // local h2 slice [il][b] (4KB)
    __shared__ ull   s_comb[128 * 2 * 4];  // [fl][ff][p] (8KB)
    __shared__ int   s_sel[Bq];
    const int tid = threadIdx.x, blk = blockIdx.x;
    ull* s_hu = (ull*)s_h;

    const int fc = blk % 14;
    const int r3 = blk / 14;
    const int ic = r3 & 7;
    const int m  = (r3 >> 3) & 1;
    const int e  = r3 >> 4;

    if (tid < Bq) s_sel[tid] = g_selG[tid];
    // load h2 slice rows [ic*128, ic*128+128): 1024 floats = 256 float4
    ((float4*)s_h)[tid] = ((const float4*)(g_h2t + ic * 128 * Bq))[tid];
    __syncthreads();

    bool used = false;
#pragma unroll
    for (int b = 0; b < Bq; b++) used |= (s_sel[b] == e);
    if (!used) return;

    const int half = tid >> 7;           // 0/1 -> local rows 0-63 / 64-127
    const int fl   = tid & 127;
    const int f    = fc * 256 + fl * 2;
    const int ibl  = half * 64;
    const float* wp = (m ? uw : gw) + (size_t)e * Dq * Fq
                    + (size_t)(ic * 128 + ibl) * Fq + f;

    ull acc[2][4];
#pragma unroll
    for (int ff = 0; ff < 2; ff++)
#pragma unroll
        for (int p = 0; p < 4; p++) acc[ff][p] = 0;

    float2 wa[8], wb[8];
#pragma unroll
    for (int u = 0; u < 8; u++) wa[u] = *(const float2*)(wp + (size_t)u * Fq);
#pragma unroll
    for (int r8 = 0; r8 < 8; r8++) {
        if (r8 < 7) {
#pragma unroll
            for (int u = 0; u < 8; u++)
                wb[u] = *(const float2*)(wp + (size_t)((r8 + 1) * 8 + u) * Fq);
        }
        int il = ibl + r8 * 8;
#pragma unroll
        for (int u = 0; u < 8; u++) {
            ull wx = pack2(wa[u].x, wa[u].x);
            ull wy = pack2(wa[u].y, wa[u].y);
#pragma unroll
            for (int p = 0; p < 4; p++) {
                ull h2 = s_hu[(il + u) * 4 + p];
                FMA2(acc[0][p], h2, wx);
                FMA2(acc[1][p], h2, wy);
            }
        }
#pragma unroll
        for (int u = 0; u < 8; u++) wa[u] = wb[u];
    }

    if (half == 1) {
#pragma unroll
        for (int ff = 0; ff < 2; ff++)
#pragma unroll
            for (int p = 0; p < 4; p++) s_comb[fl * 8 + ff * 4 + p] = acc[ff][p];
    }
    __syncthreads();
    if (half == 0) {
        float* dst = (m ? g_accu : g_accg) + (size_t)e * Bq * Fq + f;
#pragma unroll
        for (int ff = 0; ff < 2; ff++) {
#pragma unroll
            for (int p = 0; p < 4; p++) {
                ADD2(acc[ff][p], s_comb[fl * 8 + ff * 4 + p]);
                float lo, hi; unpack2(acc[ff][p], lo, hi);
                atomicAdd(&dst[(size_t)(2 * p) * Fq + ff], lo);
                atomicAdd(&dst[(size_t)(2 * p + 1) * Fq + ff], hi);
            }
        }
    }
}

// ============ K4: silu/mask + down, float2 + double-buffered. 256 blocks ============
// blk: dc(2 of 512 d) fastest, then fc(64 of 56 f), e. grid = 256.
__global__ void __launch_bounds__(256, 3) k4_down(const float* __restrict__ dw)
{
    __shared__ float s_t[56 * Bq];
    __shared__ int   s_sel[Bq];
    __shared__ float s_tw[Bq];
    const int tid = threadIdx.x, blk = blockIdx.x;
    ull* s_tu = (ull*)s_t;

    if (tid < Bq) { s_sel[tid] = g_selG[tid]; s_tw[tid] = g_twG[tid]; }
    __syncthreads();
    const int dc = blk & 1;
    const int fc = (blk >> 1) & 63;
    const int e  = blk >> 7;
    bool used = false;
#pragma unroll
    for (int b = 0; b < Bq; b++) used |= (s_sel[b] == e);
    if (!used) return;

    const int f0 = fc * 56;
    for (int idx = tid; idx < 448; idx += 256) {
        int fl = idx >> 3, b = idx & 7;
        float tv = 0.f;
        if (s_sel[b] == e) {
            int f = f0 + fl;
            float gg = g_accg[((size_t)e * Bq + b) * Fq + f];
            float uu = g_accu[((size_t)e * Bq + b) * Fq + f];
            tv = s_tw[b] * gg * (1.f / (1.f + expf(-gg))) * uu;
        }
        s_t[fl * 8 + b] = tv;
    }
    __syncthreads();

    const int d = dc * 512 + tid * 2;
    const float* dp = dw + ((size_t)e * Fq + f0) * Dq + d;
    ull acc[2][4];
#pragma unroll
    for (int dd = 0; dd < 2; dd++)
#pragma unroll
        for (int p = 0; p < 4; p++) acc[dd][p] = 0;

    float2 wa[8], wb[8];
#pragma unroll
    for (int u = 0; u < 8; u++) wa[u] = *(const float2*)(dp + (size_t)u * Dq);
#pragma unroll
    for (int r8 = 0; r8 < 7; r8++) {
        if (r8 < 6) {
#pragma unroll
            for (int u = 0; u < 8; u++)
                wb[u] = *(const float2*)(dp + (size_t)((r8 + 1) * 8 + u) * Dq);
        }
#pragma unroll
        for (int u = 0; u < 8; u++) {
            ull wx = pack2(wa[u].x, wa[u].x);
            ull wy = pack2(wa[u].y, wa[u].y);
#pragma unroll
            for (int p = 0; p < 4; p++) {
                ull t2 = s_tu[(r8 * 8 + u) * 4 + p];
                FMA2(acc[0][p], t2, wx);
                FMA2(acc[1][p], t2, wy);
            }
        }
#pragma unroll
        for (int u = 0; u < 8; u++) wa[u] = wb[u];
    }
#pragma unroll
    for (int dd = 0; dd < 2; dd++)
#pragma unroll
        for (int p = 0; p < 4; p++) {
            float lo, hi; unpack2(acc[dd][p], lo, hi);
            atomicAdd(&g_y[(2 * p) * Dq + d + dd], lo);
            atomicAdd(&g_y[(2 * p + 1) * Dq + d + dd], hi);
        }
}

// ============ K5: final rmsnorm + score head ============
__global__ void __launch_bounds__(256) k5_final(
    const float* __restrict__ hidden, const float* __restrict__ flnw,
    const float* __restrict__ sw, float* __restrict__ out)
{
    __shared__ float s_red[8 * 8];
    __shared__ float s_out[8];
    __shared__ float s_rs[1];
    const int tid = threadIdx.x, b = blockIdx.x;
    float xr[4];
    float ssv[1]; ssv[0] = 0.f;
#pragma unroll
    for (int it = 0; it < 4; it++) {
        int d = tid + it * 256;
        xr[it] = hidden[(size_t)b * Sq * Dq + d] + g_attn[b * Dq + d] + g_y[b * Dq + d];
        ssv[0] += xr[it] * xr[it];
    }
    breduce<1, 8>(ssv, s_red, s_out);
    if (tid == 0) s_rs[0] = rsqrtf(s_out[0] * (1.f / Dq) + EPSq);
    __syncthreads();
    float rs = s_rs[0];
    float p[2]; p[0] = 0.f; p[1] = 0.f;
#pragma unroll
    for (int it = 0; it < 4; it++) {
        int d = tid + it * 256;
        float xn = xr[it] * rs * flnw[d];
        p[0] = fmaf(xn, sw[d * 2 + 0], p[0]);
        p[1] = fmaf(xn, sw[d * 2 + 1], p[1]);
    }
    breduce<2, 8>(p, s_red, s_out);
    if (tid == 0) {
        out[b * 2 + 0] = s_out[0];
        out[b * 2 + 1] = s_out[1];
    }
}

// ---------------- launch ----------------
extern "C" void kernel_launch(void* const* d_in, const int* in_sizes, int n_in,
                              void* d_out, int out_size) {
    (void)in_sizes; (void)n_in; (void)out_size;
    const float* hidden = (const float*)d_in[0];
    const float* ln1w   = (const float*)d_in[1];
    // d_in[2]=q_w, d_in[3]=k_w: provably unused (causal token-0 softmax == 1)
    const float* vw     = (const float*)d_in[4];
    const float* ow     = (const float*)d_in[5];
    const float* ln2w   = (const float*)d_in[6];
    const float* rw     = (const float*)d_in[7];
    const float* gw     = (const float*)d_in[8];
    const float* uw     = (const float*)d_in[9];
    const float* dw     = (const float*)d_in[10];
    const float* flnw   = (const float*)d_in[11];
    const float* sw     = (const float*)d_in[12];
    float* out = (float*)d_out;

    k1_prep_v<<<256, 256>>>(hidden, ln1w, vw);
    k2_o<<<256, 256>>>(ow);
    k2b_h2<<<Bq, 256>>>(hidden, ln2w, rw);
    k3_gateup<<<448, 256>>>(gw, uw);
    k4_down<<<256, 256>>>(dw);
    k5_final<<<Bq, 256>>>(hidden, flnw, sw, out);
}